// round 15
// baseline (speedup 1.0000x reference)
#include <cuda_runtime.h>
#include <cuda_bf16.h>
#include <mma.h>
#include <cstdint>

using namespace nvcuda;

#define D_BINS 59
#define C_CH   80
#define O_TOT  139
#define B_     4
#define N_     6
#define CIN    256
#define H_     16
#define W_     44
#define HW     704              // H_*W_
#define NPIX   (B_*N_*H_*W_)    // 16896 = 132 * 128
#define NCELL  (B_*128*128)     // 65536
#define BEVW   128
#define CAP    64               // Poisson(15.2), P(>=64)~1e-28/cell — safe
#define STAGE  32
#define GCELLS 32
#define NOUT   144              // padded N
#define KC     32               // K-chunk
#define ASTR   40               // smem stride (bf16), 80B = 16B-multiple
#define BSTR   40
#define DSTR   61               // s_dep row stride

// ---- device scratch (no allocations; zero-initialized at load) ----
__device__ float g_ctx[NPIX*C_CH];         // [pix][c] fp32 ctx, 5.4 MB (L2-resident)
__device__ int   g_cnt[NCELL];             // per-cell counts (reset by gather)
__device__ int2  g_bin[NCELL*CAP];         // {pix, depth-bits}, 33.5 MB
__device__ __align__(16) __nv_bfloat16 g_wbf[2*NOUT*CIN];   // W hi/lo, 144 KB

// ============================================================================
// K0: prep — convert weights to bf16 hi/lo once (132 CTAs would otherwise
// each re-load + re-convert the same 142 KB of fp32 weights).
// ============================================================================
__global__ void prep_w_kernel(const float* __restrict__ wd)
{
    int i = blockIdx.x * blockDim.x + threadIdx.x;   // 0 .. NOUT*CIN-1
    if (i < NOUT * CIN) {
        int o = i >> 8;
        int c = i & 255;
        float w = (o < O_TOT) ? __ldg(&wd[o * CIN + c]) : 0.f;
        __nv_bfloat16 h = __float2bfloat16(w);
        __nv_bfloat16 l = __float2bfloat16(w - __bfloat162float(h));
        g_wbf[i]              = h;
        g_wbf[NOUT * CIN + i] = l;
    }
}

// ============================================================================
// K1: wmma bf16-split GEMM + FUSED softmax(59) + cell binning.
// CTA = 128px x 144o x K256, 384 thr = 12 warps (4M x 3N), warp tile 32x48.
// D = Xh*Wh + Xh*Wl + Xl*Wh (bf16 hi/lo split, fp32 accum, err ~1.5e-5).
// 1 CTA/SM (regs) -> staging latency hidden via REGISTER PREFETCH: chunk
// ck+1's global loads are issued before computing chunk ck.
// ============================================================================
__global__ __launch_bounds__(384) void gemm_fused_kernel(
    const float* __restrict__ img, const float* __restrict__ bd,
    const int*   __restrict__ geom)
{
    __shared__ __align__(16) char smem_buf[46592];
    // staging layout (GEMM phase)
    __nv_bfloat16* sAh = (__nv_bfloat16*)smem_buf;            // 10240
    __nv_bfloat16* sAl = sAh + 128 * ASTR;                    // +10240
    __nv_bfloat16* sBh = (__nv_bfloat16*)(smem_buf + 20480);  // 11520
    __nv_bfloat16* sBl = sBh + NOUT * BSTR;                   // +11520 = 43520
    // epilogue layout (reused after final sync)
    float* scr  = (float*)smem_buf;                           // 12*320*4 = 15360
    float* sdep = (float*)(smem_buf + 15360);                 // 128*61*4 = 31232

    const int tid  = threadIdx.x;
    const int warp = tid >> 5;
    const int lane = tid & 31;
    const int wm   = warp & 3;        // 0..3  (M)
    const int wn   = warp >> 2;       // 0..2  (N)
    const int px0  = blockIdx.x * 128;
    const uint2* wsrc = (const uint2*)g_wbf;   // 4 bf16 per uint2

    float aReg[11];
    uint2 bReg[6];

    // --- prefetch helpers (indexing fixed per thread; ck varies) ---
    auto loadA = [&](int ck) {
#pragma unroll
        for (int r = 0; r < 11; r++) {
            int i = tid + 384 * r;
            if (i < 128 * KC) {
                int c    = i >> 7;
                int px_l = i & 127;
                int px = px0 + px_l;
                int bn = px / HW;
                int hw = px - bn * HW;
                aReg[r] = __ldg(&img[(size_t)bn * CIN * HW + (ck * KC + c) * HW + hw]);
            }
        }
    };
    auto loadB = [&](int ck) {
        // 2 halves x 144 o x 8 uint2 (32 c) = 2304 uint2 = 384*6
#pragma unroll
        for (int r = 0; r < 6; r++) {
            int idx  = tid + 384 * r;
            int half = idx / 1152;
            int j    = idx - half * 1152;
            int o    = j >> 3;
            int cq   = (j & 7) * 4;              // c offset (4 bf16 = 1 uint2)
            bReg[r] = __ldg(&wsrc[(half * NOUT * CIN + o * CIN + ck * KC + cq) >> 2]);
        }
    };

    wmma::fragment<wmma::accumulator, 16, 16, 16, float> cf[2][3];
#pragma unroll
    for (int mt = 0; mt < 2; mt++)
#pragma unroll
        for (int nt = 0; nt < 3; nt++) wmma::fill_fragment(cf[mt][nt], 0.f);

    loadA(0);
    loadB(0);

    for (int ck = 0; ck < 8; ck++) {
        __syncthreads();     // previous compute done -> smem reusable
        // ---- STS staged regs (A: convert to hi/lo; B: raw uint2 copies) ----
#pragma unroll
        for (int r = 0; r < 11; r++) {
            int i = tid + 384 * r;
            if (i < 128 * KC) {
                int c    = i >> 7;
                int px_l = i & 127;
                float x = aReg[r];
                __nv_bfloat16 h = __float2bfloat16(x);
                __nv_bfloat16 l = __float2bfloat16(x - __bfloat162float(h));
                sAh[px_l * ASTR + c] = h;
                sAl[px_l * ASTR + c] = l;
            }
        }
#pragma unroll
        for (int r = 0; r < 6; r++) {
            int idx  = tid + 384 * r;
            int half = idx / 1152;
            int j    = idx - half * 1152;
            int o    = j >> 3;
            int cq   = (j & 7) * 4;
            __nv_bfloat16* dst = (half == 0) ? sBh : sBl;
            *(uint2*)&dst[o * BSTR + cq] = bReg[r];
        }
        // ---- issue NEXT chunk's loads (drain under the MMAs below) ----
        if (ck < 7) { loadA(ck + 1); loadB(ck + 1); }
        __syncthreads();

        // ---- compute: 2 k-steps x 3 terms x (2m x 3n) tiles ----
#pragma unroll
        for (int ks = 0; ks < 2; ks++) {
            wmma::fragment<wmma::matrix_a, 16, 16, 16, __nv_bfloat16, wmma::row_major> ah[2], al[2];
#pragma unroll
            for (int mt = 0; mt < 2; mt++) {
                const int arow = wm * 32 + mt * 16;
                wmma::load_matrix_sync(ah[mt], &sAh[arow * ASTR + ks * 16], ASTR);
                wmma::load_matrix_sync(al[mt], &sAl[arow * ASTR + ks * 16], ASTR);
            }
#pragma unroll
            for (int nt = 0; nt < 3; nt++) {
                const int brow = wn * 48 + nt * 16;
                wmma::fragment<wmma::matrix_b, 16, 16, 16, __nv_bfloat16, wmma::col_major> bh, bl;
                wmma::load_matrix_sync(bh, &sBh[brow * BSTR + ks * 16], BSTR);
                wmma::load_matrix_sync(bl, &sBl[brow * BSTR + ks * 16], BSTR);
#pragma unroll
                for (int mt = 0; mt < 2; mt++) {
                    wmma::mma_sync(cf[mt][nt], ah[mt], bh, cf[mt][nt]);
                    wmma::mma_sync(cf[mt][nt], ah[mt], bl, cf[mt][nt]);
                    wmma::mma_sync(cf[mt][nt], al[mt], bh, cf[mt][nt]);
                }
            }
        }
    }

    // ---- tile scatter: depth (+bias) -> sdep smem; ctx (+bias) -> g_ctx ----
    __syncthreads();
    float* wscr = scr + warp * 320;    // 16 x 20 tile
#pragma unroll
    for (int mt = 0; mt < 2; mt++) {
#pragma unroll
        for (int nt = 0; nt < 3; nt++) {
            wmma::store_matrix_sync(wscr, cf[mt][nt], 20, wmma::mem_row_major);
            __syncwarp();
#pragma unroll
            for (int e = 0; e < 8; e++) {
                int idx = lane + e * 32;
                int r   = idx >> 4;
                int col = idx & 15;
                int o = wn * 48 + nt * 16 + col;
                int p_l = wm * 32 + mt * 16 + r;
                if (o < O_TOT) {
                    float v = wscr[r * 20 + col] + __ldg(&bd[o]);
                    if (o < D_BINS) sdep[p_l * DSTR + o] = v;
                    else            g_ctx[(px0 + p_l) * C_CH + (o - D_BINS)] = v;
                }
            }
            __syncwarp();
        }
    }
    __syncthreads();

    // ---- softmax in smem: one warp per pixel (12 warps round-robin) ----
    for (int px_l = warp; px_l < 128; px_l += 12) {
        float* dp = &sdep[px_l * DSTR];
        float v0 = (lane < D_BINS)        ? dp[lane]      : -1e30f;
        float v1 = ((lane + 32) < D_BINS) ? dp[lane + 32] : -1e30f;
        float m = fmaxf(v0, v1);
#pragma unroll
        for (int off = 16; off; off >>= 1)
            m = fmaxf(m, __shfl_xor_sync(0xffffffffu, m, off));
        float e0 = (lane < D_BINS)        ? expf(v0 - m) : 0.f;
        float e1 = ((lane + 32) < D_BINS) ? expf(v1 - m) : 0.f;
        float s = e0 + e1;
#pragma unroll
        for (int off = 16; off; off >>= 1)
            s += __shfl_xor_sync(0xffffffffu, s, off);
        float inv = 1.0f / s;
        if (lane < D_BINS)        dp[lane]      = e0 * inv;
        if ((lane + 32) < D_BINS) dp[lane + 32] = e1 * inv;
    }
    __syncthreads();

    // ---- bin the CTA's 7552 points (geom reads coalesced along px) ----
    {
        const int2* g2 = (const int2*)geom;
        for (int i = tid; i < D_BINS * 128; i += 384) {
            int d    = i >> 7;
            int px_l = i & 127;
            int px = px0 + px_l;
            int bn = px / HW;
            int hw = px - bn * HW;
            int b  = bn / N_;
            int2 g = __ldg(&g2[(bn * D_BINS + d) * HW + hw]);
            int cell = (b << 14) + g.x * BEVW + g.y;
            int slot = atomicAdd(&g_cnt[cell], 1);
            if (slot < CAP)
                g_bin[cell * CAP + slot] =
                    make_int2(px, __float_as_int(sdep[px_l * DSTR + d]));
        }
    }
}

// ============================================================================
// K3: GATHER per BEV cell (unchanged from R14 measured-best).
// ============================================================================
__global__ __launch_bounds__(128, 8) void gather_kernel(float* __restrict__ out)
{
    __shared__ int2  s_rec[GCELLS * STAGE];
    __shared__ int   s_cnt[GCELLS];
    __shared__ float t[C_CH * (GCELLS + 1)];

    const int tid  = threadIdx.x;
    const int warp = tid >> 5;
    const int lane = tid & 31;
    const int b    = blockIdx.x >> 9;
    const int yx0  = (blockIdx.x & 511) * GCELLS;
    const int cell0 = (b << 14) + yx0;
    const float4* ctx4 = (const float4*)g_ctx;

    if (tid < GCELLS) {
        int c = g_cnt[cell0 + tid];
        g_cnt[cell0 + tid] = 0;
        s_cnt[tid] = (c > CAP) ? CAP : c;
    }
#pragma unroll
    for (int r = 0; r < GCELLS * STAGE / 128; r++) {
        int i  = tid + 128 * r;
        int cl = i >> 5, slot = i & 31;
        s_rec[i] = g_bin[(cell0 + cl) * CAP + slot];
    }
    __syncthreads();

#pragma unroll
    for (int cp = 0; cp < 4; cp++) {
        const int cl0 = warp * 8 + cp * 2;
        const int cl1 = cl0 + 1;
        const int cnt0 = s_cnt[cl0];
        const int cnt1 = s_cnt[cl1];
        const int c0s = (cnt0 < STAGE) ? cnt0 : STAGE;
        const int c1s = (cnt1 < STAGE) ? cnt1 : STAGE;
        const int2* rec0 = &s_rec[cl0 * STAGE];
        const int2* rec1 = &s_rec[cl1 * STAGE];
        const int maxc = (c0s > c1s) ? c0s : c1s;

        float4 acc0 = make_float4(0.f, 0.f, 0.f, 0.f);
        float4 acc1 = make_float4(0.f, 0.f, 0.f, 0.f);
        for (int base = 0; base < maxc; base += 4) {
            int   pixA[4], pixB[4];
            float depA[4], depB[4];
#pragma unroll
            for (int u = 0; u < 4; u++) {
                int pt = base + u;
                int2 rA = rec0[(pt < c0s) ? pt : 0];
                int2 rB = rec1[(pt < c1s) ? pt : 0];
                pixA[u] = rA.x;  depA[u] = (pt < c0s) ? __int_as_float(rA.y) : 0.f;
                pixB[u] = rB.x;  depB[u] = (pt < c1s) ? __int_as_float(rB.y) : 0.f;
            }
            if (lane < 20) {
#pragma unroll
                for (int u = 0; u < 4; u++) {
                    float4 cvA = __ldg(&ctx4[pixA[u] * 20 + lane]);
                    float4 cvB = __ldg(&ctx4[pixB[u] * 20 + lane]);
                    acc0.x += depA[u] * cvA.x; acc0.y += depA[u] * cvA.y;
                    acc0.z += depA[u] * cvA.z; acc0.w += depA[u] * cvA.w;
                    acc1.x += depB[u] * cvB.x; acc1.y += depB[u] * cvB.y;
                    acc1.z += depB[u] * cvB.z; acc1.w += depB[u] * cvB.w;
                }
            }
        }
        for (int pt = STAGE; pt < cnt0; pt++) {
            int2 rr = __ldg(&g_bin[(cell0 + cl0) * CAP + pt]);
            float d0 = __int_as_float(rr.y);
            if (lane < 20) {
                float4 cv = __ldg(&ctx4[rr.x * 20 + lane]);
                acc0.x += d0 * cv.x; acc0.y += d0 * cv.y;
                acc0.z += d0 * cv.z; acc0.w += d0 * cv.w;
            }
        }
        for (int pt = STAGE; pt < cnt1; pt++) {
            int2 rr = __ldg(&g_bin[(cell0 + cl1) * CAP + pt]);
            float d0 = __int_as_float(rr.y);
            if (lane < 20) {
                float4 cv = __ldg(&ctx4[rr.x * 20 + lane]);
                acc1.x += d0 * cv.x; acc1.y += d0 * cv.y;
                acc1.z += d0 * cv.z; acc1.w += d0 * cv.w;
            }
        }
        if (lane < 20) {
            int c = lane * 4;
            t[(c + 0) * (GCELLS + 1) + cl0] = acc0.x;
            t[(c + 1) * (GCELLS + 1) + cl0] = acc0.y;
            t[(c + 2) * (GCELLS + 1) + cl0] = acc0.z;
            t[(c + 3) * (GCELLS + 1) + cl0] = acc0.w;
            t[(c + 0) * (GCELLS + 1) + cl1] = acc1.x;
            t[(c + 1) * (GCELLS + 1) + cl1] = acc1.y;
            t[(c + 2) * (GCELLS + 1) + cl1] = acc1.z;
            t[(c + 3) * (GCELLS + 1) + cl1] = acc1.w;
        }
    }
    __syncthreads();

    float* dst = out + ((size_t)b * C_CH) * (128 * 128) + yx0;
#pragma unroll
    for (int i = tid; i < C_CH * GCELLS; i += 128) {
        int c = i >> 5;
        int j = i & 31;
        dst[(size_t)c * (128 * 128) + j] = t[c * (GCELLS + 1) + j];
    }
}

// ============================================================================
extern "C" void kernel_launch(void* const* d_in, const int* in_sizes, int n_in,
                              void* d_out, int out_size)
{
    const float* img  = (const float*)d_in[0];
    const float* wd   = (const float*)d_in[4];
    const float* bd   = (const float*)d_in[5];
    const int*   geom = (const int*)d_in[6];
    float* out = (float*)d_out;

    prep_w_kernel<<<(NOUT * CIN + 255) / 256, 256>>>(wd);
    gemm_fused_kernel<<<NPIX / 128, 384>>>(img, bd, geom);
    gather_kernel<<<2048, 128>>>(out);
}

// round 16
// speedup vs baseline: 1.0761x; 1.0761x over previous
#include <cuda_runtime.h>
#include <cuda_bf16.h>
#include <mma.h>
#include <cstdint>

using namespace nvcuda;

#define D_BINS 59
#define C_CH   80
#define O_TOT  139
#define B_     4
#define N_     6
#define CIN    256
#define H_     16
#define W_     44
#define HW     704              // H_*W_
#define NPIX   (B_*N_*H_*W_)    // 16896 = 264 * 64
#define NCELL  (B_*128*128)     // 65536
#define BEVW   128
#define CAP    64               // Poisson(15.2), P(>=64)~1e-28/cell — safe
#define STAGE  32
#define GCELLS 32
#define NOUT   144              // padded N
#define KC     32               // K-chunk
#define ASTR   40               // smem stride (bf16), 80B = 16B-multiple
#define BSTR   40
#define DSTR   61               // s_dep row stride

// ---- device scratch (no allocations; zero-initialized at load) ----
__device__ float g_ctx[NPIX*C_CH];         // [pix][c] fp32 ctx, 5.4 MB (L2-resident)
__device__ int   g_cnt[NCELL];             // per-cell counts (reset by gather)
__device__ int2  g_bin[NCELL*CAP];         // {pix, depth-bits}, 33.5 MB

// ============================================================================
// K1: wmma bf16-split GEMM + FUSED softmax(59) + cell binning.
// CTA = 64px x 144o x K256, 384 thr = 12 warps (4M x 3N), warp tile 16x48.
// 2 CTAs/SM (launch_bounds(384,2), 33.3KB smem, accum only 24 regs):
// 24 warps/SM so one CTA's staging overlaps the other's MMA chains — the
// occupancy fix for the MMA-latency-bound profile (R13: tensor 21.6%,
// issue 22.8%, occ 18.6%, nothing saturated).
// D = Xh*Wh + Xh*Wl + Xl*Wh (bf16 hi/lo split, fp32 accum, err ~1.5e-5).
// ============================================================================
__global__ __launch_bounds__(384, 2) void gemm_fused_kernel(
    const float* __restrict__ img, const float* __restrict__ wd,
    const float* __restrict__ bd,  const int*   __restrict__ geom)
{
    __shared__ __align__(16) char smem_buf[33280];
    // staging layout (GEMM phase)
    __nv_bfloat16* sAh = (__nv_bfloat16*)smem_buf;            // 64*40*2 = 5120
    __nv_bfloat16* sAl = sAh + 64 * ASTR;                     // +5120 = 10240
    __nv_bfloat16* sBh = (__nv_bfloat16*)(smem_buf + 10240);  // 144*40*2 = 11520
    __nv_bfloat16* sBl = sBh + NOUT * BSTR;                   // +11520 = 33280
    // epilogue layout (reused after final sync)
    float* scr  = (float*)smem_buf;                           // 12*320*4 = 15360
    float* sdep = (float*)(smem_buf + 15360);                 // 64*61*4 = 15616

    const int tid  = threadIdx.x;
    const int warp = tid >> 5;
    const int lane = tid & 31;
    const int wm   = warp & 3;        // 0..3  (M, 16 px each)
    const int wn   = warp >> 2;       // 0..2  (N, 48 o each)
    const int px0  = blockIdx.x * 64;

    wmma::fragment<wmma::accumulator, 16, 16, 16, float> cf[3];
#pragma unroll
    for (int nt = 0; nt < 3; nt++) wmma::fill_fragment(cf[nt], 0.f);

    for (int ck = 0; ck < 8; ck++) {
        __syncthreads();
        // ---- stage A: 64 px x 32 c (coalesced along px) ----
#pragma unroll
        for (int r = 0; r < 6; r++) {
            int i = tid + 384 * r;
            if (i < 64 * KC) {
                int c    = i >> 6;
                int px_l = i & 63;
                int px = px0 + px_l;
                int bn = px / HW;
                int hw = px - bn * HW;
                float x = __ldg(&img[(size_t)bn * CIN * HW + (ck * KC + c) * HW + hw]);
                __nv_bfloat16 h = __float2bfloat16(x);
                __nv_bfloat16 l = __float2bfloat16(x - __bfloat162float(h));
                sAh[px_l * ASTR + c] = h;
                sAl[px_l * ASTR + c] = l;
            }
        }
        // ---- stage B: 144 o x 32 c (coalesced along c) ----
#pragma unroll
        for (int r = 0; r < 12; r++) {
            int i = tid + 384 * r;
            if (i < NOUT * KC) {
                int n = i >> 5;
                int c = i & 31;
                float w = (n < O_TOT) ? __ldg(&wd[n * CIN + ck * KC + c]) : 0.f;
                __nv_bfloat16 h = __float2bfloat16(w);
                __nv_bfloat16 l = __float2bfloat16(w - __bfloat162float(h));
                sBh[n * BSTR + c] = h;
                sBl[n * BSTR + c] = l;
            }
        }
        __syncthreads();

        // ---- compute: 2 k-steps x 3 terms x 3 n-tiles (warp M = 16) ----
#pragma unroll
        for (int ks = 0; ks < 2; ks++) {
            wmma::fragment<wmma::matrix_a, 16, 16, 16, __nv_bfloat16, wmma::row_major> ah, al;
            const int arow = wm * 16;
            wmma::load_matrix_sync(ah, &sAh[arow * ASTR + ks * 16], ASTR);
            wmma::load_matrix_sync(al, &sAl[arow * ASTR + ks * 16], ASTR);
#pragma unroll
            for (int nt = 0; nt < 3; nt++) {
                const int brow = wn * 48 + nt * 16;
                wmma::fragment<wmma::matrix_b, 16, 16, 16, __nv_bfloat16, wmma::col_major> bh, bl;
                wmma::load_matrix_sync(bh, &sBh[brow * BSTR + ks * 16], BSTR);
                wmma::load_matrix_sync(bl, &sBl[brow * BSTR + ks * 16], BSTR);
                wmma::mma_sync(cf[nt], ah, bh, cf[nt]);
                wmma::mma_sync(cf[nt], ah, bl, cf[nt]);
                wmma::mma_sync(cf[nt], al, bh, cf[nt]);
            }
        }
    }

    // ---- tile scatter: depth (+bias) -> sdep smem; ctx (+bias) -> g_ctx ----
    __syncthreads();
    float* wscr = scr + warp * 320;    // 16 x 20 tile
#pragma unroll
    for (int nt = 0; nt < 3; nt++) {
        wmma::store_matrix_sync(wscr, cf[nt], 20, wmma::mem_row_major);
        __syncwarp();
#pragma unroll
        for (int e = 0; e < 8; e++) {
            int idx = lane + e * 32;         // 0..255 = 16x16
            int r   = idx >> 4;
            int col = idx & 15;
            int o = wn * 48 + nt * 16 + col;
            int p_l = wm * 16 + r;
            if (o < O_TOT) {
                float v = wscr[r * 20 + col] + __ldg(&bd[o]);
                if (o < D_BINS) sdep[p_l * DSTR + o] = v;
                else            g_ctx[(px0 + p_l) * C_CH + (o - D_BINS)] = v;
            }
        }
        __syncwarp();
    }
    __syncthreads();

    // ---- softmax in smem: one warp per pixel (12 warps over 64 px) ----
    for (int px_l = warp; px_l < 64; px_l += 12) {
        float* dp = &sdep[px_l * DSTR];
        float v0 = (lane < D_BINS)        ? dp[lane]      : -1e30f;
        float v1 = ((lane + 32) < D_BINS) ? dp[lane + 32] : -1e30f;
        float m = fmaxf(v0, v1);
#pragma unroll
        for (int off = 16; off; off >>= 1)
            m = fmaxf(m, __shfl_xor_sync(0xffffffffu, m, off));
        float e0 = (lane < D_BINS)        ? expf(v0 - m) : 0.f;
        float e1 = ((lane + 32) < D_BINS) ? expf(v1 - m) : 0.f;
        float s = e0 + e1;
#pragma unroll
        for (int off = 16; off; off >>= 1)
            s += __shfl_xor_sync(0xffffffffu, s, off);
        float inv = 1.0f / s;
        if (lane < D_BINS)        dp[lane]      = e0 * inv;
        if ((lane + 32) < D_BINS) dp[lane + 32] = e1 * inv;
    }
    __syncthreads();

    // ---- bin the CTA's 3776 points (geom reads coalesced along px) ----
    {
        const int2* g2 = (const int2*)geom;
        for (int i = tid; i < D_BINS * 64; i += 384) {
            int d    = i >> 6;
            int px_l = i & 63;
            int px = px0 + px_l;
            int bn = px / HW;
            int hw = px - bn * HW;
            int b  = bn / N_;
            int2 g = __ldg(&g2[(bn * D_BINS + d) * HW + hw]);
            int cell = (b << 14) + g.x * BEVW + g.y;
            int slot = atomicAdd(&g_cnt[cell], 1);
            if (slot < CAP)
                g_bin[cell * CAP + slot] =
                    make_int2(px, __float_as_int(sdep[px_l * DSTR + d]));
        }
    }
}

// ============================================================================
// K3: GATHER per BEV cell (unchanged from R14 measured-best: 41.5 us).
// ============================================================================
__global__ __launch_bounds__(128, 8) void gather_kernel(float* __restrict__ out)
{
    __shared__ int2  s_rec[GCELLS * STAGE];
    __shared__ int   s_cnt[GCELLS];
    __shared__ float t[C_CH * (GCELLS + 1)];

    const int tid  = threadIdx.x;
    const int warp = tid >> 5;
    const int lane = tid & 31;
    const int b    = blockIdx.x >> 9;
    const int yx0  = (blockIdx.x & 511) * GCELLS;
    const int cell0 = (b << 14) + yx0;
    const float4* ctx4 = (const float4*)g_ctx;

    if (tid < GCELLS) {
        int c = g_cnt[cell0 + tid];
        g_cnt[cell0 + tid] = 0;
        s_cnt[tid] = (c > CAP) ? CAP : c;
    }
#pragma unroll
    for (int r = 0; r < GCELLS * STAGE / 128; r++) {
        int i  = tid + 128 * r;
        int cl = i >> 5, slot = i & 31;
        s_rec[i] = g_bin[(cell0 + cl) * CAP + slot];
    }
    __syncthreads();

#pragma unroll
    for (int cp = 0; cp < 4; cp++) {
        const int cl0 = warp * 8 + cp * 2;
        const int cl1 = cl0 + 1;
        const int cnt0 = s_cnt[cl0];
        const int cnt1 = s_cnt[cl1];
        const int c0s = (cnt0 < STAGE) ? cnt0 : STAGE;
        const int c1s = (cnt1 < STAGE) ? cnt1 : STAGE;
        const int2* rec0 = &s_rec[cl0 * STAGE];
        const int2* rec1 = &s_rec[cl1 * STAGE];
        const int maxc = (c0s > c1s) ? c0s : c1s;

        float4 acc0 = make_float4(0.f, 0.f, 0.f, 0.f);
        float4 acc1 = make_float4(0.f, 0.f, 0.f, 0.f);
        for (int base = 0; base < maxc; base += 4) {
            int   pixA[4], pixB[4];
            float depA[4], depB[4];
#pragma unroll
            for (int u = 0; u < 4; u++) {
                int pt = base + u;
                int2 rA = rec0[(pt < c0s) ? pt : 0];
                int2 rB = rec1[(pt < c1s) ? pt : 0];
                pixA[u] = rA.x;  depA[u] = (pt < c0s) ? __int_as_float(rA.y) : 0.f;
                pixB[u] = rB.x;  depB[u] = (pt < c1s) ? __int_as_float(rB.y) : 0.f;
            }
            if (lane < 20) {
#pragma unroll
                for (int u = 0; u < 4; u++) {
                    float4 cvA = __ldg(&ctx4[pixA[u] * 20 + lane]);
                    float4 cvB = __ldg(&ctx4[pixB[u] * 20 + lane]);
                    acc0.x += depA[u] * cvA.x; acc0.y += depA[u] * cvA.y;
                    acc0.z += depA[u] * cvA.z; acc0.w += depA[u] * cvA.w;
                    acc1.x += depB[u] * cvB.x; acc1.y += depB[u] * cvB.y;
                    acc1.z += depB[u] * cvB.z; acc1.w += depB[u] * cvB.w;
                }
            }
        }
        for (int pt = STAGE; pt < cnt0; pt++) {
            int2 rr = __ldg(&g_bin[(cell0 + cl0) * CAP + pt]);
            float d0 = __int_as_float(rr.y);
            if (lane < 20) {
                float4 cv = __ldg(&ctx4[rr.x * 20 + lane]);
                acc0.x += d0 * cv.x; acc0.y += d0 * cv.y;
                acc0.z += d0 * cv.z; acc0.w += d0 * cv.w;
            }
        }
        for (int pt = STAGE; pt < cnt1; pt++) {
            int2 rr = __ldg(&g_bin[(cell0 + cl1) * CAP + pt]);
            float d0 = __int_as_float(rr.y);
            if (lane < 20) {
                float4 cv = __ldg(&ctx4[rr.x * 20 + lane]);
                acc1.x += d0 * cv.x; acc1.y += d0 * cv.y;
                acc1.z += d0 * cv.z; acc1.w += d0 * cv.w;
            }
        }
        if (lane < 20) {
            int c = lane * 4;
            t[(c + 0) * (GCELLS + 1) + cl0] = acc0.x;
            t[(c + 1) * (GCELLS + 1) + cl0] = acc0.y;
            t[(c + 2) * (GCELLS + 1) + cl0] = acc0.z;
            t[(c + 3) * (GCELLS + 1) + cl0] = acc0.w;
            t[(c + 0) * (GCELLS + 1) + cl1] = acc1.x;
            t[(c + 1) * (GCELLS + 1) + cl1] = acc1.y;
            t[(c + 2) * (GCELLS + 1) + cl1] = acc1.z;
            t[(c + 3) * (GCELLS + 1) + cl1] = acc1.w;
        }
    }
    __syncthreads();

    float* dst = out + ((size_t)b * C_CH) * (128 * 128) + yx0;
#pragma unroll
    for (int i = tid; i < C_CH * GCELLS; i += 128) {
        int c = i >> 5;
        int j = i & 31;
        dst[(size_t)c * (128 * 128) + j] = t[c * (GCELLS + 1) + j];
    }
}

// ============================================================================
extern "C" void kernel_launch(void* const* d_in, const int* in_sizes, int n_in,
                              void* d_out, int out_size)
{
    const float* img  = (const float*)d_in[0];
    const float* wd   = (const float*)d_in[4];
    const float* bd   = (const float*)d_in[5];
    const int*   geom = (const int*)d_in[6];
    float* out = (float*)d_out;

    gemm_fused_kernel<<<NPIX / 64, 384>>>(img, wd, bd, geom);
    gather_kernel<<<2048, 128>>>(out);
}